// round 14
// baseline (speedup 1.0000x reference)
#include <cuda_runtime.h>
#include <cuda_fp16.h>
#include <math.h>
#include <stdint.h>

#define NNODE 150000
#define NEDGE 300000
#define NB    4096
#define DIN   155
#define KPADX 192           // DIN padded to 3*64
#define DE    6
#define HID   256
#define NH    4
#define CC    64
#define NLAY  4
#define NEGSL 0.2f
#define EPSV  1e-5f
#define NSCAN_BLK ((NNODE + 255) / 256)   // 586

// ---------------- scratch (static device globals; no allocation) -------------
__device__ float g_xh[NNODE*HID];
__device__ float g_out[NNODE*HID];
__device__ float g_lattr[NNODE*DE];
__device__ float g_deg[NNODE];
__device__ float g_as[NNODE*NH];
__device__ float g_ad[NNODE*NH];
__device__ float g_we[NLAY*DE*NH];
__device__ float g_bnsum[2*HID];
__device__ float g_bnab[2*HID];
__device__ float g_pool[NB*HID];
__device__ float g_z1[NB*128];
__device__ float g_z2[NB*64];
// fp16 planes: h lives as a SINGLE fp16 plane (2^-11 quant); x is hi/lo exact
__device__ __align__(16) __half g_pAhi[NNODE*HID];
__device__ __align__(16) __half g_pBhi[NNODE*HID];
__device__ __align__(16) __half g_pBlo[NNODE*HID];
__device__ __align__(16) __half g_wtHi[NLAY*HID*HID];
__device__ __align__(16) __half g_wtLo[NLAY*HID*HID];
__device__ __align__(16) __half g_wtHi0[HID*KPADX];
__device__ __align__(16) __half g_wtLo0[HID*KPADX];
// CSR
__device__ int  g_indeg[NNODE];
__device__ int  g_off[NNODE + 1];
__device__ int  g_cursor[NNODE];
__device__ int  g_bsum[1024];
__device__ int2 g_csr[NEDGE];

// ---------------- helpers ----------------------------------------------------
__device__ __forceinline__ uint32_t smem_to_u32(const void* p) {
    uint32_t a;
    asm("{ .reg .u64 t; cvta.to.shared.u64 t, %1; cvt.u32.u64 %0, t; }" : "=r"(a) : "l"(p));
    return a;
}
__device__ __forceinline__ void cp_async16(uint32_t dst, const void* src, int bytes) {
    asm volatile("cp.async.cg.shared.global [%0], [%1], 16, %2;\n"
                 :: "r"(dst), "l"(src), "r"(bytes));
}
__device__ __forceinline__ void ldmx4(uint32_t r[4], uint32_t addr) {
    asm volatile("ldmatrix.sync.aligned.m8n8.x4.shared.b16 {%0,%1,%2,%3}, [%4];"
                 : "=r"(r[0]), "=r"(r[1]), "=r"(r[2]), "=r"(r[3]) : "r"(addr));
}
__device__ __forceinline__ void mma_f16(float c[4], const uint32_t a[4],
                                        uint32_t b0, uint32_t b1) {
    asm volatile("mma.sync.aligned.m16n8k16.row.col.f32.f16.f16.f32 "
                 "{%0,%1,%2,%3},{%4,%5,%6,%7},{%8,%9},{%0,%1,%2,%3};\n"
                 : "+f"(c[0]), "+f"(c[1]), "+f"(c[2]), "+f"(c[3])
                 : "r"(a[0]), "r"(a[1]), "r"(a[2]), "r"(a[3]), "r"(b0), "r"(b1));
}

// ---------------- fp16 split tensor-core GEMM --------------------------------
// 512 threads, 128x256 output tile per CTA. A+B double-buffered per 64-wide
// k-chunk. APLANES=2: A hi/lo, 3 MMAs (exact, input proj). APLANES=1: A single
// fp16 plane, 2 MMAs (Ah*Bh + Ah*Bl; weight split keeps B exact to 2^-22).
#define ST_BYTES 98304
#define A_OFS(buf,p) ((buf)*ST_BYTES + (p)*16384)
#define B_OFS(buf,p) ((buf)*ST_BYTES + 32768 + (p)*32768)
#define GB_SMEM (2*ST_BYTES)             // 196608

template<int APLANES>
__global__ __launch_bounds__(512, 1)
void gemm_f16_kernel(const __half* __restrict__ Ahi, const __half* __restrict__ Alo,
                     const __half* __restrict__ Bhi, const __half* __restrict__ Blo,
                     int lda, int nkt, int M,
                     const float* __restrict__ bias, int doRelu,
                     float* __restrict__ outF, __half* __restrict__ outHi,
                     const float* __restrict__ attS, const float* __restrict__ attD,
                     float* __restrict__ aS, float* __restrict__ aD)
{
    extern __shared__ __align__(128) char smem[];
    const uint32_t sb = smem_to_u32(smem);
    const int tid = threadIdx.x, lane = tid & 31, wid = tid >> 5;
    const int wm = (wid & 3) * 32;        // warp row offset in 128
    const int wn = (wid >> 2) * 64;       // warp col offset in 256
    const int bm = blockIdx.x * 128;

    float c[2][8][4];
#pragma unroll
    for (int mi = 0; mi < 2; mi++)
#pragma unroll
        for (int ni = 0; ni < 8; ni++)
#pragma unroll
            for (int q = 0; q < 4; q++) c[mi][ni][q] = 0.f;

    auto loadStage = [&](int kt, int buf) {
        int k0 = kt * 64;
#pragma unroll
        for (int i = 0; i < 2 * APLANES; i++) {
            int idx = i * 512 + tid;
            int p = idx >> 10, rr = idx & 1023, row = rr >> 3, u = rr & 7;
            const __half* sp = p ? Alo : Ahi;
            int gr = bm + row;
            int bytes = (gr < M) ? 16 : 0;
            const void* src = sp + (size_t)(gr < M ? gr : 0) * lda + k0 + u * 8;
            cp_async16(sb + A_OFS(buf, p) + (uint32_t)(row * 128 + ((u ^ (row & 7)) * 16)), src, bytes);
        }
#pragma unroll
        for (int i = 0; i < 8; i++) {
            int idx = i * 512 + tid;
            int p = idx >> 11, rr = idx & 2047, row = rr >> 3, u = rr & 7;
            const __half* sp = p ? Blo : Bhi;
            const void* src = sp + (size_t)row * lda + k0 + u * 8;
            cp_async16(sb + B_OFS(buf, p) + (uint32_t)(row * 128 + ((u ^ (row & 7)) * 16)), src, 16);
        }
        asm volatile("cp.async.commit_group;\n");
    };

    auto computeStep = [&](int buf) {
#pragma unroll
        for (int ks = 0; ks < 4; ks++) {
            uint32_t a[APLANES][2][4];
#pragma unroll
            for (int plane = 0; plane < APLANES; plane++)
#pragma unroll
                for (int mi = 0; mi < 2; mi++) {
                    int row = wm + mi * 16 + ((lane >> 3) & 1) * 8 + (lane & 7);
                    int u = 2 * ks + (lane >> 4);
                    uint32_t addr = sb + A_OFS(buf, plane) + (uint32_t)(row * 128 + ((u ^ (row & 7)) * 16));
                    ldmx4(a[plane][mi], addr);
                }
            uint32_t b[2][4][4];
#pragma unroll
            for (int plane = 0; plane < 2; plane++)
#pragma unroll
                for (int ng = 0; ng < 4; ng++) {
                    int n = wn + ng * 16 + (lane >> 4) * 8 + (lane & 7);
                    int u = 2 * ks + ((lane >> 3) & 1);
                    uint32_t addr = sb + B_OFS(buf, plane) + (uint32_t)(n * 128 + ((u ^ (n & 7)) * 16));
                    ldmx4(b[plane][ng], addr);
                }
#pragma unroll
            for (int mi = 0; mi < 2; mi++)
#pragma unroll
                for (int ni = 0; ni < 8; ni++) {
                    int ng = ni >> 1, hf = (ni & 1) * 2;
                    uint32_t bh0 = b[0][ng][hf], bh1 = b[0][ng][hf + 1];
                    uint32_t bl0 = b[1][ng][hf], bl1 = b[1][ng][hf + 1];
                    mma_f16(c[mi][ni], a[0][mi], bh0, bh1);
                    mma_f16(c[mi][ni], a[0][mi], bl0, bl1);
                    if (APLANES == 2)
                        mma_f16(c[mi][ni], a[1][mi], bh0, bh1);
                }
        }
    };

    loadStage(0, 0);
    for (int kt = 0; kt < nkt; kt++) {
        if (kt + 1 < nkt) {
            loadStage(kt + 1, (kt + 1) & 1);
            asm volatile("cp.async.wait_group 1;\n");
        } else {
            asm volatile("cp.async.wait_group 0;\n");
        }
        __syncthreads();
        computeStep(kt & 1);
        __syncthreads();
    }

    // epilogue (+ optional fused attention scalars)
    float sA[2][2] = {{0.f, 0.f}, {0.f, 0.f}};
    float sD[2][2] = {{0.f, 0.f}, {0.f, 0.f}};
    const int head = wn >> 6;
#pragma unroll
    for (int mi = 0; mi < 2; mi++) {
        int r0 = bm + wm + mi * 16 + (lane >> 2);
#pragma unroll
        for (int ni = 0; ni < 8; ni++) {
            int col = wn + ni * 8 + (lane & 3) * 2;
            float bv0 = bias ? bias[col] : 0.f;
            float bv1 = bias ? bias[col + 1] : 0.f;
            float v0 = c[mi][ni][0] + bv0, v1 = c[mi][ni][1] + bv1;
            float v2 = c[mi][ni][2] + bv0, v3 = c[mi][ni][3] + bv1;
            if (doRelu) {
                v0 = fmaxf(v0, 0.f); v1 = fmaxf(v1, 0.f);
                v2 = fmaxf(v2, 0.f); v3 = fmaxf(v3, 0.f);
            }
            if (outF) {
                if (r0 < M)     *(float2*)&outF[(size_t)r0 * HID + col]       = make_float2(v0, v1);
                if (r0 + 8 < M) *(float2*)&outF[(size_t)(r0 + 8) * HID + col] = make_float2(v2, v3);
                if (aS) {
                    int ci = head * CC + (col & 63);
                    float w0s = attS[ci], w1s = attS[ci + 1];
                    float w0d = attD[ci], w1d = attD[ci + 1];
                    sA[mi][0] += v0 * w0s + v1 * w1s;
                    sA[mi][1] += v2 * w0s + v3 * w1s;
                    sD[mi][0] += v0 * w0d + v1 * w1d;
                    sD[mi][1] += v2 * w0d + v3 * w1d;
                }
            } else {
                if (r0 < M) {
                    __half2 h01; h01.x = __float2half_rn(v0); h01.y = __float2half_rn(v1);
                    *(__half2*)&outHi[(size_t)r0 * HID + col] = h01;
                }
                if (r0 + 8 < M) {
                    __half2 h23; h23.x = __float2half_rn(v2); h23.y = __float2half_rn(v3);
                    *(__half2*)&outHi[(size_t)(r0 + 8) * HID + col] = h23;
                }
            }
        }
    }
    if (outF && aS) {
#pragma unroll
        for (int mi = 0; mi < 2; mi++)
#pragma unroll
            for (int rr = 0; rr < 2; rr++) {
                float a = sA[mi][rr], d = sD[mi][rr];
                a += __shfl_xor_sync(0xFFFFFFFFu, a, 1);
                a += __shfl_xor_sync(0xFFFFFFFFu, a, 2);
                d += __shfl_xor_sync(0xFFFFFFFFu, d, 1);
                d += __shfl_xor_sync(0xFFFFFFFFu, d, 2);
                int row = bm + wm + mi * 16 + (lane >> 2) + rr * 8;
                if ((lane & 3) == 0 && row < M) {
                    aS[row * 4 + head] = a;
                    aD[row * 4 + head] = d;
                }
            }
    }
}

// ---------------- plane prep kernels -----------------------------------------
__global__ void prep_x_kernel(const float* __restrict__ x,
                              __half* __restrict__ hi, __half* __restrict__ lo)
{
    int idx = blockIdx.x * blockDim.x + threadIdx.x;
    if (idx >= NNODE * KPADX) return;
    int row = idx / KPADX, k = idx - row * KPADX;
    float v = (k < DIN) ? x[(size_t)row * DIN + k] : 0.f;
    __half h = __float2half_rn(v);
    hi[idx] = h;
    lo[idx] = __float2half_rn(v - __half2float(h));
}

__global__ void prep_wt_kernel(const float* __restrict__ W, int K, int Kpad,
                               __half* __restrict__ hi, __half* __restrict__ lo)
{
    int idx = blockIdx.x * blockDim.x + threadIdx.x;
    if (idx >= HID * Kpad) return;
    int n = idx / Kpad, k = idx - n * Kpad;
    float v = (k < K) ? W[(size_t)k * HID + n] : 0.f;
    __half h = __float2half_rn(v);
    hi[idx] = h;
    lo[idx] = __float2half_rn(v - __half2float(h));
}

__global__ void prep_wt_all_kernel(const float* __restrict__ W,
                                   __half* __restrict__ hi, __half* __restrict__ lo)
{
    int idx = blockIdx.x * blockDim.x + threadIdx.x;
    if (idx >= NLAY * HID * HID) return;
    int l = idx >> 16;
    int rc = idx & 65535;
    int n = rc >> 8, k = rc & 255;
    float v = W[(size_t)l * HID * HID + (size_t)k * HID + n];
    __half h = __float2half_rn(v);
    hi[idx] = h;
    lo[idx] = __float2half_rn(v - __half2float(h));
}

__global__ void we_all_kernel(const float* __restrict__ eW, const float* __restrict__ aE,
                              float* __restrict__ we)
{
    int t = threadIdx.x;
    if (t >= NLAY * DE * NH) return;
    int l = t / (DE * NH), r = t % (DE * NH);
    int k = r >> 2, hh = r & 3;
    float s = 0.f;
    for (int c = 0; c < CC; c++)
        s += eW[(size_t)l * DE * HID + k * HID + hh * CC + c] * aE[l * NH * CC + hh * CC + c];
    we[t] = s;
}

// ---------------- generic tiled SGEMM (small MLP matmuls) --------------------
__global__ __launch_bounds__(256)
void sgemm_kernel(const float* __restrict__ A, const float* __restrict__ B,
                  const float* __restrict__ bias, float* __restrict__ C,
                  int M, int K, int N, int doRelu)
{
    const int BM = 128, BN = 128, BK = 8;
    __shared__ float As[BK][BM + 4];
    __shared__ float Bs[BK][BN];
    int tid = threadIdx.x;
    int bm = blockIdx.y * BM, bn = blockIdx.x * BN;
    int ty = tid >> 4, tx = tid & 15;
    float acc[8][8];
#pragma unroll
    for (int i = 0; i < 8; i++)
#pragma unroll
        for (int j = 0; j < 8; j++) acc[i][j] = 0.f;

    for (int k0 = 0; k0 < K; k0 += BK) {
#pragma unroll
        for (int i = 0; i < 4; i++) {
            int l = tid + i * 256;
            int r = l >> 3, c = l & 7;
            int gr = bm + r, gc = k0 + c;
            As[c][r] = (gr < M && gc < K) ? A[(size_t)gr * K + gc] : 0.f;
        }
#pragma unroll
        for (int i = 0; i < 4; i++) {
            int l = tid + i * 256;
            int r = l >> 7, c = l & 127;
            int gr = k0 + r, gc = bn + c;
            Bs[r][c] = (gr < K && gc < N) ? B[(size_t)gr * N + gc] : 0.f;
        }
        __syncthreads();
#pragma unroll
        for (int k = 0; k < BK; k++) {
            float4 av0 = *(const float4*)&As[k][ty * 8];
            float4 av1 = *(const float4*)&As[k][ty * 8 + 4];
            float4 bv0 = *(const float4*)&Bs[k][tx * 8];
            float4 bv1 = *(const float4*)&Bs[k][tx * 8 + 4];
            float ar[8] = {av0.x, av0.y, av0.z, av0.w, av1.x, av1.y, av1.z, av1.w};
            float br[8] = {bv0.x, bv0.y, bv0.z, bv0.w, bv1.x, bv1.y, bv1.z, bv1.w};
#pragma unroll
            for (int i = 0; i < 8; i++)
#pragma unroll
                for (int j = 0; j < 8; j++) acc[i][j] += ar[i] * br[j];
        }
        __syncthreads();
    }
#pragma unroll
    for (int i = 0; i < 8; i++) {
        int gr = bm + ty * 8 + i;
        if (gr >= M) continue;
#pragma unroll
        for (int j = 0; j < 8; j++) {
            int gc = bn + tx * 8 + j;
            if (gc >= N) continue;
            float v = acc[i][j];
            if (bias) v += bias[gc];
            if (doRelu) v = fmaxf(v, 0.f);
            C[(size_t)gr * N + gc] = v;
        }
    }
}

// ---------------- self-loop attr + in-degree count ---------------------------
__global__ void edge_deg_kernel(const int* __restrict__ ei, const float* __restrict__ eattr,
                                float* __restrict__ deg, float* __restrict__ lattr,
                                int* __restrict__ indeg)
{
    int e = blockIdx.x * blockDim.x + threadIdx.x;
    if (e >= NEDGE) return;
    int d = ei[NEDGE + e];
    atomicAdd(&deg[d], 1.f);
    atomicAdd(&indeg[d], 1);
#pragma unroll
    for (int k = 0; k < DE; k++) atomicAdd(&lattr[d * DE + k], eattr[e * DE + k]);
}

__global__ void loop_norm_kernel(const float* __restrict__ deg, float* __restrict__ lattr)
{
    int n = blockIdx.x * blockDim.x + threadIdx.x;
    if (n >= NNODE) return;
    float inv = 1.f / fmaxf(deg[n], 1.f);
#pragma unroll
    for (int k = 0; k < DE; k++) lattr[n * DE + k] *= inv;
}

// ---------------- CSR build: scan + fill -------------------------------------
__global__ void scan_block_reduce(const int* __restrict__ cnt, int* __restrict__ bsum)
{
    __shared__ int s[256];
    int i = blockIdx.x * 256 + threadIdx.x;
    s[threadIdx.x] = (i < NNODE) ? cnt[i] : 0;
    __syncthreads();
    for (int o = 128; o; o >>= 1) {
        if (threadIdx.x < o) s[threadIdx.x] += s[threadIdx.x + o];
        __syncthreads();
    }
    if (threadIdx.x == 0) bsum[blockIdx.x] = s[0];
}

__global__ void scan_bsum_kernel(int* __restrict__ bsum)
{
    __shared__ int s[1024];
    int t = threadIdx.x;
    int v = (t < NSCAN_BLK) ? bsum[t] : 0;
    s[t] = v;
    for (int o = 1; o < 1024; o <<= 1) {
        __syncthreads();
        int u = (t >= o) ? s[t - o] : 0;
        __syncthreads();
        s[t] += u;
    }
    if (t < NSCAN_BLK) bsum[t] = s[t] - v;   // exclusive
}

__global__ void scan_offsets_kernel(const int* __restrict__ cnt, const int* __restrict__ bsum,
                                    int* __restrict__ off, int* __restrict__ cursor)
{
    __shared__ int s[256];
    int i = blockIdx.x * 256 + threadIdx.x;
    int v = (i < NNODE) ? cnt[i] : 0;
    s[threadIdx.x] = v;
    for (int o = 1; o < 256; o <<= 1) {
        __syncthreads();
        int u = (threadIdx.x >= o) ? s[threadIdx.x - o] : 0;
        __syncthreads();
        s[threadIdx.x] += u;
    }
    __syncthreads();
    int excl = s[threadIdx.x] - v + bsum[blockIdx.x];
    if (i < NNODE) { off[i] = excl; cursor[i] = excl; }
    if (i == NNODE - 1) off[NNODE] = excl + v;
}

__global__ void csr_fill_kernel(const int* __restrict__ ei, int* __restrict__ cursor,
                                int2* __restrict__ csr)
{
    int e = blockIdx.x * blockDim.x + threadIdx.x;
    if (e >= NEDGE) return;
    int d = ei[NEDGE + e];
    int pos = atomicAdd(&cursor[d], 1);
    csr[pos] = make_int2(ei[e], e);
}

// ---------------- fused GAT online softmax + aggregate + BN stats ------------
// warp per dst node (256 thr = 8 nodes/block); epilogue stages out+gb into a
// bank-conflict-free smem buffer, block-reduces, 512 global REDs per block.
__global__ __launch_bounds__(256)
void gat_aggregate_kernel(const int2* __restrict__ csr, const int* __restrict__ off,
                          const float* __restrict__ eattr, const float* __restrict__ lattr,
                          const float* __restrict__ we,
                          const float* __restrict__ a_s, const float* __restrict__ a_d,
                          const float* __restrict__ xh, const float* __restrict__ gb,
                          float* __restrict__ out, float* __restrict__ bnsum)
{
    __shared__ float stage[256][9];     // [col][warp] (+1 pad: odd stride, no conflicts)
    const int tid = threadIdx.x, lane = tid & 31, wid = tid >> 5;
    const int n = blockIdx.x * 8 + wid;
    const int myh = lane >> 3;

    if (n < NNODE) {
        const int lo = off[n], hi = off[n + 1];
        float wmy[DE];
#pragma unroll
        for (int k = 0; k < DE; k++) wmy[k] = we[k * 4 + myh];
        const float adv = a_d[n * 4 + myh];

        float m;
        {
            float l = a_s[n * 4 + myh] + adv;
            const float* la = &lattr[(size_t)n * DE];
#pragma unroll
            for (int k = 0; k < DE; k++) l += la[k] * wmy[k];
            m = l > 0.f ? l : NEGSL * l;
        }
        float den = 1.f;
        float acc[8];
        {
            const float4* xr = (const float4*)(xh + (size_t)n * HID + lane * 8);
            float4 v0 = xr[0], v1 = xr[1];
            acc[0] = v0.x; acc[1] = v0.y; acc[2] = v0.z; acc[3] = v0.w;
            acc[4] = v1.x; acc[5] = v1.y; acc[6] = v1.z; acc[7] = v1.w;
        }

        for (int e = lo; e < hi; e++) {
            int2 p = csr[e];
            float l = a_s[p.x * 4 + myh] + adv;
            const float* ea = &eattr[(size_t)p.y * DE];
#pragma unroll
            for (int k = 0; k < DE; k++) l += ea[k] * wmy[k];
            l = l > 0.f ? l : NEGSL * l;
            float nm = fmaxf(m, l);
            float so = __expf(m - nm);
            float ex = __expf(l - nm);
            m = nm;
            den = den * so + ex;
            const float4* xr = (const float4*)(xh + (size_t)p.x * HID + lane * 8);
            float4 v0 = xr[0], v1 = xr[1];
            acc[0] = acc[0] * so + ex * v0.x; acc[1] = acc[1] * so + ex * v0.y;
            acc[2] = acc[2] * so + ex * v0.z; acc[3] = acc[3] * so + ex * v0.w;
            acc[4] = acc[4] * so + ex * v1.x; acc[5] = acc[5] * so + ex * v1.y;
            acc[6] = acc[6] * so + ex * v1.z; acc[7] = acc[7] * so + ex * v1.w;
        }

        float inv = 1.f / den;
        float f[8];
#pragma unroll
        for (int j = 0; j < 8; j++) f[j] = acc[j] * inv;
        float* orow = out + (size_t)n * HID + lane * 8;
        *(float4*)&orow[0] = make_float4(f[0], f[1], f[2], f[3]);
        *(float4*)&orow[4] = make_float4(f[4], f[5], f[6], f[7]);
#pragma unroll
        for (int j = 0; j < 8; j++)
            stage[lane * 8 + j][wid] = f[j] + gb[lane * 8 + j];
    } else {
#pragma unroll
        for (int j = 0; j < 8; j++)
            stage[lane * 8 + j][wid] = 0.f;
    }
    __syncthreads();
    // block reduce: thread t owns column t
    {
        float s = 0.f, s2 = 0.f;
#pragma unroll
        for (int w = 0; w < 8; w++) {
            float v = stage[tid][w];
            s += v; s2 += v * v;
        }
        atomicAdd(&bnsum[tid], s);
        atomicAdd(&bnsum[HID + tid], s2);
    }
}

// ---------------- batchnorm ---------------------------------------------------
__global__ void bn_reset_kernel(float* __restrict__ bnsum)
{
    int t = threadIdx.x;
    if (t < 2 * HID) bnsum[t] = 0.f;
}

// computes ab and self-zeros bnsum for the next layer
__global__ void bn_finalize_kernel(float* __restrict__ bnsum,
                                   const float* __restrict__ gamma, const float* __restrict__ beta,
                                   float* __restrict__ ab)
{
    __shared__ float s[512];
    int t = threadIdx.x;   // 512 threads
    s[t] = bnsum[t];
    bnsum[t] = 0.f;
    __syncthreads();
    if (t < HID) {
        float mu  = s[t] / (float)NNODE;
        float var = s[HID + t] / (float)NNODE - mu * mu;
        float a = gamma[t] * rsqrtf(var + EPSV);
        ab[t] = a;
        ab[HID + t] = beta[t] - mu * a;
    }
}

// fused: bn affine + relu + residual (prev fp16 plane) -> fp16 plane
__global__ void bn_apply_kernel(const float* __restrict__ out, const float* __restrict__ gb,
                                const float* __restrict__ ab,
                                const __half* __restrict__ prevHi, int res,
                                __half* __restrict__ pHi)
{
    int idx = blockIdx.x * blockDim.x + threadIdx.x;
    int c = threadIdx.x;
    float v = out[idx] + gb[c];
    v = v * ab[c] + ab[HID + c];
    v = fmaxf(v, 0.f);
    if (res) v += __half2float(prevHi[idx]);
    pHi[idx] = __float2half_rn(v);
}

// ---------------- pooling with fused final BN boundary ------------------------
__global__ void pool_bn_kernel(const float* __restrict__ out, const float* __restrict__ gb,
                               const float* __restrict__ ab,
                               const __half* __restrict__ resHi,
                               const int* __restrict__ bidx, float* __restrict__ g)
{
    int b = blockIdx.x;
    int t = threadIdx.x;
    __shared__ int slo, shi;
    if (t == 0) {
        int lo = 0, hi = NNODE;
        while (lo < hi) { int mid = (lo + hi) >> 1; if (bidx[mid] < b) lo = mid + 1; else hi = mid; }
        slo = lo;
        hi = NNODE;
        while (lo < hi) { int mid = (lo + hi) >> 1; if (bidx[mid] < b + 1) lo = mid + 1; else hi = mid; }
        shi = lo;
    }
    __syncthreads();
    int lo = slo, hi = shi;
    float a_ = ab[t], b_ = ab[HID + t], gv = gb[t];
    float s = 0.f;
    for (int r = lo; r < hi; r++) {
        float v = fmaxf((out[(size_t)r * HID + t] + gv) * a_ + b_, 0.f);
        v += __half2float(resHi[(size_t)r * HID + t]);
        s += v;
    }
    g[b * HID + t] = s / fmaxf((float)(hi - lo), 1.f);
}

// ---------------- final dot with p_W3 ----------------------------------------
__global__ void final_kernel(const float* __restrict__ z2, const float* __restrict__ w3,
                             const float* __restrict__ b3, float* __restrict__ outp)
{
    int gw = (blockIdx.x * blockDim.x + threadIdx.x) >> 5;
    int lane = threadIdx.x & 31;
    if (gw >= NB) return;
    float v = z2[gw * 64 + lane] * w3[lane] + z2[gw * 64 + lane + 32] * w3[lane + 32];
#pragma unroll
    for (int o = 16; o; o >>= 1) v += __shfl_xor_sync(0xFFFFFFFFu, v, o);
    if (lane == 0) outp[gw] = v + b3[0];
}

// ---------------- host orchestration -----------------------------------------
extern "C" void kernel_launch(void* const* d_in, const int* in_sizes, int n_in,
                              void* d_out, int out_size)
{
    int o = (n_in >= 21) ? 0 : -1;
    const float* x      = (const float*)d_in[0];
    const int*   ei     = (const int*)  d_in[1];
    const float* eattr  = (const float*)d_in[2];
    const int*   bidx   = (const int*)  d_in[3];
    const float* in_W   = (const float*)d_in[5 + o];
    const float* in_b   = (const float*)d_in[6 + o];
    const float* gat_W  = (const float*)d_in[7 + o];
    const float* attS   = (const float*)d_in[8 + o];
    const float* attD   = (const float*)d_in[9 + o];
    const float* edge_W = (const float*)d_in[10 + o];
    const float* attE   = (const float*)d_in[11 + o];
    const float* gat_b  = (const float*)d_in[12 + o];
    const float* bn_g   = (const float*)d_in[13 + o];
    const float* bn_b   = (const float*)d_in[14 + o];
    const float* p_W1   = (const float*)d_in[15 + o];
    const float* p_b1   = (const float*)d_in[16 + o];
    const float* p_W2   = (const float*)d_in[17 + o];
    const float* p_b2   = (const float*)d_in[18 + o];
    const float* p_W3   = (const float*)d_in[19 + o];
    const float* p_b3   = (const float*)d_in[20 + o];
    float* outp = (float*)d_out;

    float *xh, *outb, *lattr, *deg, *as_, *ad_, *we, *bnsum, *bnab, *pool, *z1, *z2;
    __half *pAhi, *pBhi, *pBlo, *wtHi, *wtLo, *wtHi0, *wtLo0;
    int *indeg, *off, *cursor, *bsum;
    int2 *csr;
    cudaGetSymbolAddress((void**)&xh,    g_xh);
    cudaGetSymbolAddress((void**)&outb,  g_out);
    cudaGetSymbolAddress((void**)&lattr, g_lattr);
    cudaGetSymbolAddress((void**)&deg,   g_deg);
    cudaGetSymbolAddress((void**)&as_,   g_as);
    cudaGetSymbolAddress((void**)&ad_,   g_ad);
    cudaGetSymbolAddress((void**)&we,    g_we);
    cudaGetSymbolAddress((void**)&bnsum, g_bnsum);
    cudaGetSymbolAddress((void**)&bnab,  g_bnab);
    cudaGetSymbolAddress((void**)&pool,  g_pool);
    cudaGetSymbolAddress((void**)&z1,    g_z1);
    cudaGetSymbolAddress((void**)&z2,    g_z2);
    cudaGetSymbolAddress((void**)&pAhi,  g_pAhi);
    cudaGetSymbolAddress((void**)&pBhi,  g_pBhi);
    cudaGetSymbolAddress((void**)&pBlo,  g_pBlo);
    cudaGetSymbolAddress((void**)&wtHi,  g_wtHi);
    cudaGetSymbolAddress((void**)&wtLo,  g_wtLo);
    cudaGetSymbolAddress((void**)&wtHi0, g_wtHi0);
    cudaGetSymbolAddress((void**)&wtLo0, g_wtLo0);
    cudaGetSymbolAddress((void**)&indeg, g_indeg);
    cudaGetSymbolAddress((void**)&off,   g_off);
    cudaGetSymbolAddress((void**)&cursor,g_cursor);
    cudaGetSymbolAddress((void**)&bsum,  g_bsum);
    cudaGetSymbolAddress((void**)&csr,   g_csr);

    cudaFuncSetAttribute(gemm_f16_kernel<1>,
                         cudaFuncAttributeMaxDynamicSharedMemorySize, GB_SMEM);
    cudaFuncSetAttribute(gemm_f16_kernel<2>,
                         cudaFuncAttributeMaxDynamicSharedMemorySize, GB_SMEM);

    const int NTILE = (NNODE + 127) / 128;   // 1172

    cudaMemsetAsync(deg, 0, NNODE * sizeof(float));
    cudaMemsetAsync(lattr, 0, NNODE * DE * sizeof(float));
    cudaMemsetAsync(indeg, 0, NNODE * sizeof(int));
    prep_x_kernel<<<(NNODE * KPADX + 255) / 256, 256>>>(x, pBhi, pBlo);
    prep_wt_kernel<<<(HID * KPADX + 255) / 256, 256>>>(in_W, DIN, KPADX, wtHi0, wtLo0);
    // edge_deg placed before the gemm so ncu -s 5 lands on the gemm
    edge_deg_kernel<<<(NEDGE + 255) / 256, 256>>>(ei, eattr, deg, lattr, indeg);
    // input projection: x planes (pB hi/lo, 3-MMA exact) -> h_pre fp16 plane (pA)
    gemm_f16_kernel<2><<<NTILE, 512, GB_SMEM>>>(
        pBhi, pBlo, wtHi0, wtLo0, KPADX, 3, NNODE, in_b, 1,
        nullptr, pAhi, nullptr, nullptr, nullptr, nullptr);

    // graph prep (rest)
    loop_norm_kernel<<<(NNODE + 255) / 256, 256>>>(deg, lattr);
    scan_block_reduce<<<NSCAN_BLK, 256>>>(indeg, bsum);
    scan_bsum_kernel<<<1, 1024>>>(bsum);
    scan_offsets_kernel<<<NSCAN_BLK, 256>>>(indeg, bsum, off, cursor);
    csr_fill_kernel<<<(NEDGE + 255) / 256, 256>>>(ei, cursor, csr);

    // batched per-layer constants
    we_all_kernel<<<1, 128>>>(edge_W, attE, we);
    prep_wt_all_kernel<<<(NLAY * HID * HID + 255) / 256, 256>>>(gat_W, wtHi, wtLo);
    bn_reset_kernel<<<1, 512>>>(bnsum);

    // layer loop: h planes ping-pong pAhi <-> pBhi (single fp16 planes)
    __half* pin = pAhi;
    for (int i = 0; i < NLAY; i++) {
        gemm_f16_kernel<1><<<NTILE, 512, GB_SMEM>>>(
            pin, nullptr, wtHi + (size_t)i * HID * HID, wtLo + (size_t)i * HID * HID,
            HID, 4, NNODE, nullptr, 0, xh, nullptr,
            attS + i * NH * CC, attD + i * NH * CC, as_, ad_);
        gat_aggregate_kernel<<<(NNODE + 7) / 8, 256>>>(
            csr, off, eattr, lattr, we + i * DE * NH, as_, ad_, xh,
            gat_b + i * HID, outb, bnsum);
        bn_finalize_kernel<<<1, 512>>>(bnsum, bn_g + i * HID, bn_b + i * HID, bnab);
        if (i < NLAY - 1) {
            __half* po = (i & 1) ? pAhi : pBhi;
            bn_apply_kernel<<<NNODE, 256>>>(outb, gat_b + i * HID, bnab, pin,
                                            i > 0 ? 1 : 0, po);
            pin = po;
        }
    }

    // boundary 3 fused into pooling: h3 = relu(bn(out_3)) + h_2 (pin plane)
    pool_bn_kernel<<<NB, 256>>>(outb, gat_b + 3 * HID, bnab, pin, bidx, pool);
    sgemm_kernel<<<dim3(1, (NB + 127) / 128), 256>>>(pool, p_W1, p_b1, z1, NB, HID, 128, 1);
    sgemm_kernel<<<dim3(1, (NB + 127) / 128), 256>>>(z1, p_W2, p_b2, z2, NB, 128, 64, 1);
    final_kernel<<<(NB * 32 + 255) / 256, 256>>>(z2, p_W3, p_b3, outp);
}

// round 17
// speedup vs baseline: 1.2158x; 1.2158x over previous
#include <cuda_runtime.h>
#include <cuda_fp16.h>
#include <math.h>
#include <stdint.h>

#define NNODE 150000
#define NEDGE 300000
#define NB    4096
#define DIN   155
#define KPADX 192           // DIN padded to 3*64
#define DE    6
#define HID   256
#define NH    4
#define CC    64
#define NLAY  4
#define NEGSL 0.2f
#define EPSV  1e-5f
#define NSCAN_BLK ((NNODE + 255) / 256)   // 586

// ---------------- scratch (static device globals; no allocation) -------------
__device__ float g_xh[NNODE*HID];
__device__ float g_out[NNODE*HID];
__device__ float g_lattr[NNODE*DE];
__device__ float g_deg[NNODE];
__device__ float g_as[NNODE*NH];
__device__ float g_ad[NNODE*NH];
__device__ float g_we[NLAY*DE*NH];
__device__ float g_bnsum[2*HID];
__device__ float g_bnab[2*HID];
__device__ float g_pool[NB*HID];
__device__ float g_z1[NB*128];
__device__ float g_z2[NB*64];
// fp16 planes: h lives as a SINGLE fp16 plane (2^-11 quant); x is hi/lo exact
__device__ __align__(16) __half g_pAhi[NNODE*HID];
__device__ __align__(16) __half g_pBhi[NNODE*HID];
__device__ __align__(16) __half g_pBlo[NNODE*HID];
__device__ __align__(16) __half g_wtHi[NLAY*HID*HID];
__device__ __align__(16) __half g_wtLo[NLAY*HID*HID];
__device__ __align__(16) __half g_wtHi0[HID*KPADX];
__device__ __align__(16) __half g_wtLo0[HID*KPADX];
// CSR
__device__ int  g_indeg[NNODE];
__device__ int  g_off[NNODE + 1];
__device__ int  g_cursor[NNODE];
__device__ int  g_bsum[1024];
__device__ int2 g_csr[NEDGE];

// ---------------- helpers ----------------------------------------------------
__device__ __forceinline__ uint32_t smem_to_u32(const void* p) {
    uint32_t a;
    asm("{ .reg .u64 t; cvta.to.shared.u64 t, %1; cvt.u32.u64 %0, t; }" : "=r"(a) : "l"(p));
    return a;
}
__device__ __forceinline__ void cp_async16(uint32_t dst, const void* src, int bytes) {
    asm volatile("cp.async.cg.shared.global [%0], [%1], 16, %2;\n"
                 :: "r"(dst), "l"(src), "r"(bytes));
}
__device__ __forceinline__ void ldmx4(uint32_t r[4], uint32_t addr) {
    asm volatile("ldmatrix.sync.aligned.m8n8.x4.shared.b16 {%0,%1,%2,%3}, [%4];"
                 : "=r"(r[0]), "=r"(r[1]), "=r"(r[2]), "=r"(r[3]) : "r"(addr));
}
__device__ __forceinline__ void mma_f16(float c[4], const uint32_t a[4],
                                        uint32_t b0, uint32_t b1) {
    asm volatile("mma.sync.aligned.m16n8k16.row.col.f32.f16.f16.f32 "
                 "{%0,%1,%2,%3},{%4,%5,%6,%7},{%8,%9},{%0,%1,%2,%3};\n"
                 : "+f"(c[0]), "+f"(c[1]), "+f"(c[2]), "+f"(c[3])
                 : "r"(a[0]), "r"(a[1]), "r"(a[2]), "r"(a[3]), "r"(b0), "r"(b1));
}

// ---------------- fp16 split tensor-core GEMM --------------------------------
// 512 threads, 128x256 output tile per CTA. A+B double-buffered per 64-wide
// k-chunk. APLANES=2: A hi/lo, 3 MMAs (exact, input proj). APLANES=1: A single
// fp16 plane, 2 MMAs (Ah*Bh + Ah*Bl; weight split keeps B exact to 2^-22).
#define ST_BYTES 98304
#define A_OFS(buf,p) ((buf)*ST_BYTES + (p)*16384)
#define B_OFS(buf,p) ((buf)*ST_BYTES + 32768 + (p)*32768)
#define GB_SMEM (2*ST_BYTES)             // 196608

template<int APLANES>
__global__ __launch_bounds__(512, 1)
void gemm_f16_kernel(const __half* __restrict__ Ahi, const __half* __restrict__ Alo,
                     const __half* __restrict__ Bhi, const __half* __restrict__ Blo,
                     int lda, int nkt, int M,
                     const float* __restrict__ bias, int doRelu,
                     float* __restrict__ outF, __half* __restrict__ outHi,
                     const float* __restrict__ attS, const float* __restrict__ attD,
                     float* __restrict__ aS, float* __restrict__ aD)
{
    extern __shared__ __align__(128) char smem[];
    const uint32_t sb = smem_to_u32(smem);
    const int tid = threadIdx.x, lane = tid & 31, wid = tid >> 5;
    const int wm = (wid & 3) * 32;        // warp row offset in 128
    const int wn = (wid >> 2) * 64;       // warp col offset in 256
    const int bm = blockIdx.x * 128;

    float c[2][8][4];
#pragma unroll
    for (int mi = 0; mi < 2; mi++)
#pragma unroll
        for (int ni = 0; ni < 8; ni++)
#pragma unroll
            for (int q = 0; q < 4; q++) c[mi][ni][q] = 0.f;

    auto loadStage = [&](int kt, int buf) {
        int k0 = kt * 64;
#pragma unroll
        for (int i = 0; i < 2 * APLANES; i++) {
            int idx = i * 512 + tid;
            int p = idx >> 10, rr = idx & 1023, row = rr >> 3, u = rr & 7;
            const __half* sp = p ? Alo : Ahi;
            int gr = bm + row;
            int bytes = (gr < M) ? 16 : 0;
            const void* src = sp + (size_t)(gr < M ? gr : 0) * lda + k0 + u * 8;
            cp_async16(sb + A_OFS(buf, p) + (uint32_t)(row * 128 + ((u ^ (row & 7)) * 16)), src, bytes);
        }
#pragma unroll
        for (int i = 0; i < 8; i++) {
            int idx = i * 512 + tid;
            int p = idx >> 11, rr = idx & 2047, row = rr >> 3, u = rr & 7;
            const __half* sp = p ? Blo : Bhi;
            const void* src = sp + (size_t)row * lda + k0 + u * 8;
            cp_async16(sb + B_OFS(buf, p) + (uint32_t)(row * 128 + ((u ^ (row & 7)) * 16)), src, 16);
        }
        asm volatile("cp.async.commit_group;\n");
    };

    auto computeStep = [&](int buf) {
#pragma unroll
        for (int ks = 0; ks < 4; ks++) {
            uint32_t a[APLANES][2][4];
#pragma unroll
            for (int plane = 0; plane < APLANES; plane++)
#pragma unroll
                for (int mi = 0; mi < 2; mi++) {
                    int row = wm + mi * 16 + ((lane >> 3) & 1) * 8 + (lane & 7);
                    int u = 2 * ks + (lane >> 4);
                    uint32_t addr = sb + A_OFS(buf, plane) + (uint32_t)(row * 128 + ((u ^ (row & 7)) * 16));
                    ldmx4(a[plane][mi], addr);
                }
            uint32_t b[2][4][4];
#pragma unroll
            for (int plane = 0; plane < 2; plane++)
#pragma unroll
                for (int ng = 0; ng < 4; ng++) {
                    int n = wn + ng * 16 + (lane >> 4) * 8 + (lane & 7);
                    int u = 2 * ks + ((lane >> 3) & 1);
                    uint32_t addr = sb + B_OFS(buf, plane) + (uint32_t)(n * 128 + ((u ^ (n & 7)) * 16));
                    ldmx4(b[plane][ng], addr);
                }
#pragma unroll
            for (int mi = 0; mi < 2; mi++)
#pragma unroll
                for (int ni = 0; ni < 8; ni++) {
                    int ng = ni >> 1, hf = (ni & 1) * 2;
                    uint32_t bh0 = b[0][ng][hf], bh1 = b[0][ng][hf + 1];
                    uint32_t bl0 = b[1][ng][hf], bl1 = b[1][ng][hf + 1];
                    mma_f16(c[mi][ni], a[0][mi], bh0, bh1);
                    mma_f16(c[mi][ni], a[0][mi], bl0, bl1);
                    if (APLANES == 2)
                        mma_f16(c[mi][ni], a[1][mi], bh0, bh1);
                }
        }
    };

    loadStage(0, 0);
    for (int kt = 0; kt < nkt; kt++) {
        if (kt + 1 < nkt) {
            loadStage(kt + 1, (kt + 1) & 1);
            asm volatile("cp.async.wait_group 1;\n");
        } else {
            asm volatile("cp.async.wait_group 0;\n");
        }
        __syncthreads();
        computeStep(kt & 1);
        __syncthreads();
    }

    // epilogue (+ optional fused attention scalars)
    float sA[2][2] = {{0.f, 0.f}, {0.f, 0.f}};
    float sD[2][2] = {{0.f, 0.f}, {0.f, 0.f}};
    const int head = wn >> 6;
#pragma unroll
    for (int mi = 0; mi < 2; mi++) {
        int r0 = bm + wm + mi * 16 + (lane >> 2);
#pragma unroll
        for (int ni = 0; ni < 8; ni++) {
            int col = wn + ni * 8 + (lane & 3) * 2;
            float bv0 = bias ? bias[col] : 0.f;
            float bv1 = bias ? bias[col + 1] : 0.f;
            float v0 = c[mi][ni][0] + bv0, v1 = c[mi][ni][1] + bv1;
            float v2 = c[mi][ni][2] + bv0, v3 = c[mi][ni][3] + bv1;
            if (doRelu) {
                v0 = fmaxf(v0, 0.f); v1 = fmaxf(v1, 0.f);
                v2 = fmaxf(v2, 0.f); v3 = fmaxf(v3, 0.f);
            }
            if (outF) {
                if (r0 < M)     *(float2*)&outF[(size_t)r0 * HID + col]       = make_float2(v0, v1);
                if (r0 + 8 < M) *(float2*)&outF[(size_t)(r0 + 8) * HID + col] = make_float2(v2, v3);
                if (aS) {
                    int ci = head * CC + (col & 63);
                    float w0s = attS[ci], w1s = attS[ci + 1];
                    float w0d = attD[ci], w1d = attD[ci + 1];
                    sA[mi][0] += v0 * w0s + v1 * w1s;
                    sA[mi][1] += v2 * w0s + v3 * w1s;
                    sD[mi][0] += v0 * w0d + v1 * w1d;
                    sD[mi][1] += v2 * w0d + v3 * w1d;
                }
            } else {
                if (r0 < M) {
                    __half2 h01; h01.x = __float2half_rn(v0); h01.y = __float2half_rn(v1);
                    *(__half2*)&outHi[(size_t)r0 * HID + col] = h01;
                }
                if (r0 + 8 < M) {
                    __half2 h23; h23.x = __float2half_rn(v2); h23.y = __float2half_rn(v3);
                    *(__half2*)&outHi[(size_t)(r0 + 8) * HID + col] = h23;
                }
            }
        }
    }
    if (outF && aS) {
#pragma unroll
        for (int mi = 0; mi < 2; mi++)
#pragma unroll
            for (int rr = 0; rr < 2; rr++) {
                float a = sA[mi][rr], d = sD[mi][rr];
                a += __shfl_xor_sync(0xFFFFFFFFu, a, 1);
                a += __shfl_xor_sync(0xFFFFFFFFu, a, 2);
                d += __shfl_xor_sync(0xFFFFFFFFu, d, 1);
                d += __shfl_xor_sync(0xFFFFFFFFu, d, 2);
                int row = bm + wm + mi * 16 + (lane >> 2) + rr * 8;
                if ((lane & 3) == 0 && row < M) {
                    aS[row * 4 + head] = a;
                    aD[row * 4 + head] = d;
                }
            }
    }
}

// ---------------- plane prep kernels -----------------------------------------
__global__ void prep_x_kernel(const float* __restrict__ x,
                              __half* __restrict__ hi, __half* __restrict__ lo)
{
    int idx = blockIdx.x * blockDim.x + threadIdx.x;
    if (idx >= NNODE * KPADX) return;
    int row = idx / KPADX, k = idx - row * KPADX;
    float v = (k < DIN) ? x[(size_t)row * DIN + k] : 0.f;
    __half h = __float2half_rn(v);
    hi[idx] = h;
    lo[idx] = __float2half_rn(v - __half2float(h));
}

__global__ void prep_wt_kernel(const float* __restrict__ W, int K, int Kpad,
                               __half* __restrict__ hi, __half* __restrict__ lo)
{
    int idx = blockIdx.x * blockDim.x + threadIdx.x;
    if (idx >= HID * Kpad) return;
    int n = idx / Kpad, k = idx - n * Kpad;
    float v = (k < K) ? W[(size_t)k * HID + n] : 0.f;
    __half h = __float2half_rn(v);
    hi[idx] = h;
    lo[idx] = __float2half_rn(v - __half2float(h));
}

__global__ void prep_wt_all_kernel(const float* __restrict__ W,
                                   __half* __restrict__ hi, __half* __restrict__ lo)
{
    int idx = blockIdx.x * blockDim.x + threadIdx.x;
    if (idx >= NLAY * HID * HID) return;
    int l = idx >> 16;
    int rc = idx & 65535;
    int n = rc >> 8, k = rc & 255;
    float v = W[(size_t)l * HID * HID + (size_t)k * HID + n];
    __half h = __float2half_rn(v);
    hi[idx] = h;
    lo[idx] = __float2half_rn(v - __half2float(h));
}

__global__ void we_all_kernel(const float* __restrict__ eW, const float* __restrict__ aE,
                              float* __restrict__ we)
{
    int t = threadIdx.x;
    if (t >= NLAY * DE * NH) return;
    int l = t / (DE * NH), r = t % (DE * NH);
    int k = r >> 2, hh = r & 3;
    float s = 0.f;
    for (int c = 0; c < CC; c++)
        s += eW[(size_t)l * DE * HID + k * HID + hh * CC + c] * aE[l * NH * CC + hh * CC + c];
    we[t] = s;
}

// ---------------- generic tiled SGEMM (small MLP matmuls) --------------------
__global__ __launch_bounds__(256)
void sgemm_kernel(const float* __restrict__ A, const float* __restrict__ B,
                  const float* __restrict__ bias, float* __restrict__ C,
                  int M, int K, int N, int doRelu)
{
    const int BM = 128, BN = 128, BK = 8;
    __shared__ float As[BK][BM + 4];
    __shared__ float Bs[BK][BN];
    int tid = threadIdx.x;
    int bm = blockIdx.y * BM, bn = blockIdx.x * BN;
    int ty = tid >> 4, tx = tid & 15;
    float acc[8][8];
#pragma unroll
    for (int i = 0; i < 8; i++)
#pragma unroll
        for (int j = 0; j < 8; j++) acc[i][j] = 0.f;

    for (int k0 = 0; k0 < K; k0 += BK) {
#pragma unroll
        for (int i = 0; i < 4; i++) {
            int l = tid + i * 256;
            int r = l >> 3, c = l & 7;
            int gr = bm + r, gc = k0 + c;
            As[c][r] = (gr < M && gc < K) ? A[(size_t)gr * K + gc] : 0.f;
        }
#pragma unroll
        for (int i = 0; i < 4; i++) {
            int l = tid + i * 256;
            int r = l >> 7, c = l & 127;
            int gr = k0 + r, gc = bn + c;
            Bs[r][c] = (gr < K && gc < N) ? B[(size_t)gr * N + gc] : 0.f;
        }
        __syncthreads();
#pragma unroll
        for (int k = 0; k < BK; k++) {
            float4 av0 = *(const float4*)&As[k][ty * 8];
            float4 av1 = *(const float4*)&As[k][ty * 8 + 4];
            float4 bv0 = *(const float4*)&Bs[k][tx * 8];
            float4 bv1 = *(const float4*)&Bs[k][tx * 8 + 4];
            float ar[8] = {av0.x, av0.y, av0.z, av0.w, av1.x, av1.y, av1.z, av1.w};
            float br[8] = {bv0.x, bv0.y, bv0.z, bv0.w, bv1.x, bv1.y, bv1.z, bv1.w};
#pragma unroll
            for (int i = 0; i < 8; i++)
#pragma unroll
                for (int j = 0; j < 8; j++) acc[i][j] += ar[i] * br[j];
        }
        __syncthreads();
    }
#pragma unroll
    for (int i = 0; i < 8; i++) {
        int gr = bm + ty * 8 + i;
        if (gr >= M) continue;
#pragma unroll
        for (int j = 0; j < 8; j++) {
            int gc = bn + tx * 8 + j;
            if (gc >= N) continue;
            float v = acc[i][j];
            if (bias) v += bias[gc];
            if (doRelu) v = fmaxf(v, 0.f);
            C[(size_t)gr * N + gc] = v;
        }
    }
}

// ---------------- self-loop attr + in-degree count ---------------------------
__global__ void edge_deg_kernel(const int* __restrict__ ei, const float* __restrict__ eattr,
                                float* __restrict__ deg, float* __restrict__ lattr,
                                int* __restrict__ indeg)
{
    int e = blockIdx.x * blockDim.x + threadIdx.x;
    if (e >= NEDGE) return;
    int d = ei[NEDGE + e];
    atomicAdd(&deg[d], 1.f);
    atomicAdd(&indeg[d], 1);
#pragma unroll
    for (int k = 0; k < DE; k++) atomicAdd(&lattr[d * DE + k], eattr[e * DE + k]);
}

__global__ void loop_norm_kernel(const float* __restrict__ deg, float* __restrict__ lattr)
{
    int n = blockIdx.x * blockDim.x + threadIdx.x;
    if (n >= NNODE) return;
    float inv = 1.f / fmaxf(deg[n], 1.f);
#pragma unroll
    for (int k = 0; k < DE; k++) lattr[n * DE + k] *= inv;
}

// ---------------- CSR build: scan + fill -------------------------------------
__global__ void scan_block_reduce(const int* __restrict__ cnt, int* __restrict__ bsum)
{
    __shared__ int s[256];
    int i = blockIdx.x * 256 + threadIdx.x;
    s[threadIdx.x] = (i < NNODE) ? cnt[i] : 0;
    __syncthreads();
    for (int o = 128; o; o >>= 1) {
        if (threadIdx.x < o) s[threadIdx.x] += s[threadIdx.x + o];
        __syncthreads();
    }
    if (threadIdx.x == 0) bsum[blockIdx.x] = s[0];
}

__global__ void scan_bsum_kernel(int* __restrict__ bsum)
{
    __shared__ int s[1024];
    int t = threadIdx.x;
    int v = (t < NSCAN_BLK) ? bsum[t] : 0;
    s[t] = v;
    for (int o = 1; o < 1024; o <<= 1) {
        __syncthreads();
        int u = (t >= o) ? s[t - o] : 0;
        __syncthreads();
        s[t] += u;
    }
    if (t < NSCAN_BLK) bsum[t] = s[t] - v;   // exclusive
}

__global__ void scan_offsets_kernel(const int* __restrict__ cnt, const int* __restrict__ bsum,
                                    int* __restrict__ off, int* __restrict__ cursor)
{
    __shared__ int s[256];
    int i = blockIdx.x * 256 + threadIdx.x;
    int v = (i < NNODE) ? cnt[i] : 0;
    s[threadIdx.x] = v;
    for (int o = 1; o < 256; o <<= 1) {
        __syncthreads();
        int u = (threadIdx.x >= o) ? s[threadIdx.x - o] : 0;
        __syncthreads();
        s[threadIdx.x] += u;
    }
    __syncthreads();
    int excl = s[threadIdx.x] - v + bsum[blockIdx.x];
    if (i < NNODE) { off[i] = excl; cursor[i] = excl; }
    if (i == NNODE - 1) off[NNODE] = excl + v;
}

__global__ void csr_fill_kernel(const int* __restrict__ ei, int* __restrict__ cursor,
                                int2* __restrict__ csr)
{
    int e = blockIdx.x * blockDim.x + threadIdx.x;
    if (e >= NEDGE) return;
    int d = ei[NEDGE + e];
    int pos = atomicAdd(&cursor[d], 1);
    csr[pos] = make_int2(ei[e], e);
}

// ---------------- fused GAT single-pass online softmax + aggregate -----------
__global__ __launch_bounds__(256)
void gat_aggregate_kernel(const int2* __restrict__ csr, const int* __restrict__ off,
                          const float* __restrict__ eattr, const float* __restrict__ lattr,
                          const float* __restrict__ we,
                          const float* __restrict__ a_s, const float* __restrict__ a_d,
                          const float* __restrict__ xh, float* __restrict__ out)
{
    int gw = (blockIdx.x * blockDim.x + threadIdx.x) >> 5;
    int lane = threadIdx.x & 31;
    if (gw >= NNODE) return;
    const int n = gw;
    const int lo = off[n], hi = off[n + 1];
    const int myh = lane >> 3;

    float wmy[DE];
#pragma unroll
    for (int k = 0; k < DE; k++) wmy[k] = we[k * 4 + myh];
    const float adv = a_d[n * 4 + myh];

    float m;
    {
        float l = a_s[n * 4 + myh] + adv;
        const float* la = &lattr[(size_t)n * DE];
#pragma unroll
        for (int k = 0; k < DE; k++) l += la[k] * wmy[k];
        m = l > 0.f ? l : NEGSL * l;
    }
    float den = 1.f;
    float acc[8];
    {
        const float4* xr = (const float4*)(xh + (size_t)n * HID + lane * 8);
        float4 v0 = xr[0], v1 = xr[1];
        acc[0] = v0.x; acc[1] = v0.y; acc[2] = v0.z; acc[3] = v0.w;
        acc[4] = v1.x; acc[5] = v1.y; acc[6] = v1.z; acc[7] = v1.w;
    }

    for (int e = lo; e < hi; e++) {
        int2 p = csr[e];
        float l = a_s[p.x * 4 + myh] + adv;
        const float* ea = &eattr[(size_t)p.y * DE];
#pragma unroll
        for (int k = 0; k < DE; k++) l += ea[k] * wmy[k];
        l = l > 0.f ? l : NEGSL * l;
        float nm = fmaxf(m, l);
        float so = __expf(m - nm);
        float ex = __expf(l - nm);
        m = nm;
        den = den * so + ex;
        const float4* xr = (const float4*)(xh + (size_t)p.x * HID + lane * 8);
        float4 v0 = xr[0], v1 = xr[1];
        acc[0] = acc[0] * so + ex * v0.x; acc[1] = acc[1] * so + ex * v0.y;
        acc[2] = acc[2] * so + ex * v0.z; acc[3] = acc[3] * so + ex * v0.w;
        acc[4] = acc[4] * so + ex * v1.x; acc[5] = acc[5] * so + ex * v1.y;
        acc[6] = acc[6] * so + ex * v1.z; acc[7] = acc[7] * so + ex * v1.w;
    }

    float inv = 1.f / den;
    float* orow = out + (size_t)n * HID + lane * 8;
    *(float4*)&orow[0] = make_float4(acc[0] * inv, acc[1] * inv, acc[2] * inv, acc[3] * inv);
    *(float4*)&orow[4] = make_float4(acc[4] * inv, acc[5] * inv, acc[6] * inv, acc[7] * inv);
}

// ---------------- batchnorm ---------------------------------------------------
__global__ void bn_reset_kernel(float* __restrict__ bnsum)
{
    int t = threadIdx.x;
    if (t < 2 * HID) bnsum[t] = 0.f;
}

__global__ void bn_stats_kernel(const float* __restrict__ out, const float* __restrict__ gb,
                                float* __restrict__ bnsum)
{
    int t = threadIdx.x;
    int r0 = blockIdx.x * 512;
    int r1 = min(r0 + 512, NNODE);
    float gbv = gb[t];
    float s = 0.f, s2 = 0.f;
    for (int r = r0; r < r1; r++) {
        float v = out[(size_t)r * HID + t] + gbv;
        s += v; s2 += v * v;
    }
    atomicAdd(&bnsum[t], s);
    atomicAdd(&bnsum[HID + t], s2);
}

// computes ab and self-zeros bnsum for the next layer
__global__ void bn_finalize_kernel(float* __restrict__ bnsum,
                                   const float* __restrict__ gamma, const float* __restrict__ beta,
                                   float* __restrict__ ab)
{
    __shared__ float s[512];
    int t = threadIdx.x;   // 512 threads
    s[t] = bnsum[t];
    bnsum[t] = 0.f;
    __syncthreads();
    if (t < HID) {
        float mu  = s[t] / (float)NNODE;
        float var = s[HID + t] / (float)NNODE - mu * mu;
        float a = gamma[t] * rsqrtf(var + EPSV);
        ab[t] = a;
        ab[HID + t] = beta[t] - mu * a;
    }
}

// fused: bn affine + relu + residual (prev fp16 plane) -> fp16 plane
// vectorized: 4 elements per thread
__global__ void bn_apply_kernel(const float* __restrict__ out, const float* __restrict__ gb,
                                const float* __restrict__ ab,
                                const __half* __restrict__ prevHi, int res,
                                __half* __restrict__ pHi)
{
    int idx4 = blockIdx.x * blockDim.x + threadIdx.x;   // over NNODE*HID/4
    if (idx4 >= NNODE * (HID / 4)) return;
    int c = (idx4 << 2) & (HID - 1);
    float4 ov = *(const float4*)(out + (size_t)idx4 * 4);
    float4 gv = *(const float4*)(gb + c);
    float4 av = *(const float4*)(ab + c);
    float4 bv = *(const float4*)(ab + HID + c);
    float v0 = fmaxf((ov.x + gv.x) * av.x + bv.x, 0.f);
    float v1 = fmaxf((ov.y + gv.y) * av.y + bv.y, 0.f);
    float v2 = fmaxf((ov.z + gv.z) * av.z + bv.z, 0.f);
    float v3 = fmaxf((ov.w + gv.w) * av.w + bv.w, 0.f);
    if (res) {
        const __half2* rp = (const __half2*)(prevHi + (size_t)idx4 * 4);
        __half2 r01 = rp[0], r23 = rp[1];
        v0 += __half2float(r01.x); v1 += __half2float(r01.y);
        v2 += __half2float(r23.x); v3 += __half2float(r23.y);
    }
    __half2 h01, h23;
    h01.x = __float2half_rn(v0); h01.y = __float2half_rn(v1);
    h23.x = __float2half_rn(v2); h23.y = __float2half_rn(v3);
    __half2* wp = (__half2*)(pHi + (size_t)idx4 * 4);
    wp[0] = h01;
    wp[1] = h23;
}

// ---------------- pooling with fused final BN boundary ------------------------
__global__ void pool_bn_kernel(const float* __restrict__ out, const float* __restrict__ gb,
                               const float* __restrict__ ab,
                               const __half* __restrict__ resHi,
                               const int* __restrict__ bidx, float* __restrict__ g)
{
    int b = blockIdx.x;
    int t = threadIdx.x;
    __shared__ int slo, shi;
    if (t == 0) {
        int lo = 0, hi = NNODE;
        while (lo < hi) { int mid = (lo + hi) >> 1; if (bidx[mid] < b) lo = mid + 1; else hi = mid; }
        slo = lo;
        hi = NNODE;
        while (lo < hi) { int mid = (lo + hi) >> 1; if (bidx[mid] < b + 1) lo = mid + 1; else hi = mid; }
        shi = lo;
    }
    __syncthreads();
    int lo = slo, hi = shi;
    float a_ = ab[t], b_ = ab[HID + t], gv = gb[t];
    float s = 0.f;
    for (int r = lo; r < hi; r++) {
        float v = fmaxf((out[(size_t)r * HID + t] + gv) * a_ + b_, 0.f);
        v += __half2float(resHi[(size_t)r * HID + t]);
        s += v;
    }
    g[b * HID + t] = s / fmaxf((float)(hi - lo), 1.f);
}

// ---------------- final dot with p_W3 ----------------------------------------
__global__ void final_kernel(const float* __restrict__ z2, const float* __restrict__ w3,
                             const float* __restrict__ b3, float* __restrict__ outp)
{
    int gw = (blockIdx.x * blockDim.x + threadIdx.x) >> 5;
    int lane = threadIdx.x & 31;
    if (gw >= NB) return;
    float v = z2[gw * 64 + lane] * w3[lane] + z2[gw * 64 + lane + 32] * w3[lane + 32];
#pragma unroll
    for (int o = 16; o; o >>= 1) v += __shfl_xor_sync(0xFFFFFFFFu, v, o);
    if (lane == 0) outp[gw] = v + b3[0];
}

// ---------------- host orchestration -----------------------------------------
extern "C" void kernel_launch(void* const* d_in, const int* in_sizes, int n_in,
                              void* d_out, int out_size)
{
    int o = (n_in >= 21) ? 0 : -1;
    const float* x      = (const float*)d_in[0];
    const int*   ei     = (const int*)  d_in[1];
    const float* eattr  = (const float*)d_in[2];
    const int*   bidx   = (const int*)  d_in[3];
    const float* in_W   = (const float*)d_in[5 + o];
    const float* in_b   = (const float*)d_in[6 + o];
    const float* gat_W  = (const float*)d_in[7 + o];
    const float* attS   = (const float*)d_in[8 + o];
    const float* attD   = (const float*)d_in[9 + o];
    const float* edge_W = (const float*)d_in[10 + o];
    const float* attE   = (const float*)d_in[11 + o];
    const float* gat_b  = (const float*)d_in[12 + o];
    const float* bn_g   = (const float*)d_in[13 + o];
    const float* bn_b   = (const float*)d_in[14 + o];
    const float* p_W1   = (const float*)d_in[15 + o];
    const float* p_b1   = (const float*)d_in[16 + o];
    const float* p_W2   = (const float*)d_in[17 + o];
    const float* p_b2   = (const float*)d_in[18 + o];
    const float* p_W3   = (const float*)d_in[19 + o];
    const float* p_b3   = (const float*)d_in[20 + o];
    float* outp = (float*)d_out;

    float *xh, *outb, *lattr, *deg, *as_, *ad_, *we, *bnsum, *bnab, *pool, *z1, *z2;
    __half *pAhi, *pBhi, *pBlo, *wtHi, *wtLo, *wtHi0, *wtLo0;
    int *indeg, *off, *cursor, *bsum;
    int2 *csr;
    cudaGetSymbolAddress((void**)&xh,    g_xh);
    cudaGetSymbolAddress((void**)&outb,  g_out);
    cudaGetSymbolAddress((void**)&lattr, g_lattr);
    cudaGetSymbolAddress((void**)&deg,   g_deg);
    cudaGetSymbolAddress((void**)&as_,   g_as);
    cudaGetSymbolAddress((void**)&ad_,   g_ad);
    cudaGetSymbolAddress((void**)&we,    g_we);
    cudaGetSymbolAddress((void**)&bnsum, g_bnsum);
    cudaGetSymbolAddress((void**)&bnab,  g_bnab);
    cudaGetSymbolAddress((void**)&pool,  g_pool);
    cudaGetSymbolAddress((void**)&z1,    g_z1);
    cudaGetSymbolAddress((void**)&z2,    g_z2);
    cudaGetSymbolAddress((void**)&pAhi,  g_pAhi);
    cudaGetSymbolAddress((void**)&pBhi,  g_pBhi);
    cudaGetSymbolAddress((void**)&pBlo,  g_pBlo);
    cudaGetSymbolAddress((void**)&wtHi,  g_wtHi);
    cudaGetSymbolAddress((void**)&wtLo,  g_wtLo);
    cudaGetSymbolAddress((void**)&wtHi0, g_wtHi0);
    cudaGetSymbolAddress((void**)&wtLo0, g_wtLo0);
    cudaGetSymbolAddress((void**)&indeg, g_indeg);
    cudaGetSymbolAddress((void**)&off,   g_off);
    cudaGetSymbolAddress((void**)&cursor,g_cursor);
    cudaGetSymbolAddress((void**)&bsum,  g_bsum);
    cudaGetSymbolAddress((void**)&csr,   g_csr);

    cudaFuncSetAttribute(gemm_f16_kernel<1>,
                         cudaFuncAttributeMaxDynamicSharedMemorySize, GB_SMEM);
    cudaFuncSetAttribute(gemm_f16_kernel<2>,
                         cudaFuncAttributeMaxDynamicSharedMemorySize, GB_SMEM);

    const int NTILE = (NNODE + 127) / 128;   // 1172

    cudaMemsetAsync(deg, 0, NNODE * sizeof(float));
    cudaMemsetAsync(lattr, 0, NNODE * DE * sizeof(float));
    cudaMemsetAsync(indeg, 0, NNODE * sizeof(int));
    prep_x_kernel<<<(NNODE * KPADX + 255) / 256, 256>>>(x, pBhi, pBlo);
    prep_wt_kernel<<<(HID * KPADX + 255) / 256, 256>>>(in_W, DIN, KPADX, wtHi0, wtLo0);
    // edge_deg placed before the gemm so ncu -s 5 lands on the gemm
    edge_deg_kernel<<<(NEDGE + 255) / 256, 256>>>(ei, eattr, deg, lattr, indeg);
    // input projection: x planes (pB hi/lo, 3-MMA exact) -> h_pre fp16 plane (pA)
    gemm_f16_kernel<2><<<NTILE, 512, GB_SMEM>>>(
        pBhi, pBlo, wtHi0, wtLo0, KPADX, 3, NNODE, in_b, 1,
        nullptr, pAhi, nullptr, nullptr, nullptr, nullptr);

    // graph prep (rest)
    loop_norm_kernel<<<(NNODE + 255) / 256, 256>>>(deg, lattr);
    scan_block_reduce<<<NSCAN_BLK, 256>>>(indeg, bsum);
    scan_bsum_kernel<<<1, 1024>>>(bsum);
    scan_offsets_kernel<<<NSCAN_BLK, 256>>>(indeg, bsum, off, cursor);
    csr_fill_kernel<<<(NEDGE + 255) / 256, 256>>>(ei, cursor, csr);

    // batched per-layer constants
    we_all_kernel<<<1, 128>>>(edge_W, attE, we);
    prep_wt_all_kernel<<<(NLAY * HID * HID + 255) / 256, 256>>>(gat_W, wtHi, wtLo);
    bn_reset_kernel<<<1, 512>>>(bnsum);

    // layer loop: h planes ping-pong pAhi <-> pBhi (single fp16 planes)
    __half* pin = pAhi;
    for (int i = 0; i < NLAY; i++) {
        gemm_f16_kernel<1><<<NTILE, 512, GB_SMEM>>>(
            pin, nullptr, wtHi + (size_t)i * HID * HID, wtLo + (size_t)i * HID * HID,
            HID, 4, NNODE, nullptr, 0, xh, nullptr,
            attS + i * NH * CC, attD + i * NH * CC, as_, ad_);
        gat_aggregate_kernel<<<(NNODE * 32 + 255) / 256, 256>>>(
            csr, off, eattr, lattr, we + i * DE * NH, as_, ad_, xh, outb);
        bn_stats_kernel<<<(NNODE + 511) / 512, 256>>>(outb, gat_b + i * HID, bnsum);
        bn_finalize_kernel<<<1, 512>>>(bnsum, bn_g + i * HID, bn_b + i * HID, bnab);
        if (i < NLAY - 1) {
            __half* po = (i & 1) ? pAhi : pBhi;
            bn_apply_kernel<<<(NNODE * (HID / 4) + 255) / 256, 256>>>(
                outb, gat_b + i * HID, bnab, pin, i > 0 ? 1 : 0, po);
            pin = po;
        }
    }

    // boundary 3 fused into pooling: h3 = relu(bn(out_3)) + h_2 (pin plane)
    pool_bn_kernel<<<NB, 256>>>(outb, gat_b + 3 * HID, bnab, pin, bidx, pool);
    sgemm_kernel<<<dim3(1, (NB + 127) / 128), 256>>>(pool, p_W1, p_b1, z1, NB, HID, 128, 1);
    sgemm_kernel<<<dim3(1, (NB + 127) / 128), 256>>>(z1, p_W2, p_b2, z2, NB, 128, 64, 1);
    final_kernel<<<(NB * 32 + 255) / 256, 256>>>(z2, p_W3, p_b3, outp);
}